// round 13
// baseline (speedup 1.0000x reference)
#include <cuda_runtime.h>
#include <cuda_fp16.h>
#include <stdint.h>

// out[c,y,x] = sum_l alpha[idx,l,y,x] * sum_{i,j} img[c,y+i,x+j] * w[c*16+l,i,j]
//
// HMMA m16n8k16 implicit-im2col (R12 base, YB=32):
//  - rolling 4-slot A register window, slide AFTER kstep1 (row i dead)
//  - B smem chunked BY K-STEP, zero-reg ping-pong reload (>=8 MMAs LDS cover)
//  - bit4-XOR swizzle (conflict-free LDS.128)
//  - pointer-walk epilogue
//  - YB=32: halo staging overhead per output row 2.88 -> 1.94
//  - 3 blocks/SM (71.4 KB smem, ~80 regs)

#define KS     31
#define NL     16
#define HOUT   1024
#define WOUT   1024
#define IW     1054
#define HW     ((size_t)HOUT * WOUT)

#define YB     32              // output rows per block
#define IMROWS (YB + 30)       // 62 staged image rows
#define IMCOLS 158             // 128 + 30 needed columns
#define CW     80              // half2 words per copy per row
#define COPY_OFF   (CW * 4)    // 320 B: parity-shifted copy offset
#define ROWSTRIDE  (2 * CW * 4)          // 640 B per image row (both copies)
#define IMG_BYTES  (IMROWS * ROWSTRIDE)  // 39680
#define W_BYTES    (KS * 32 * 32)        // 31744: [i][lane][8 half2] (swizzled)
#define SMEM_BYTES (IMG_BYTES + W_BYTES) // 71424 -> 3 blocks/SM (214.3 KB)

#define THREADS 256

static __device__ __forceinline__ uint32_t bswz(uint32_t off) {
    return off ^ (((off >> 7) & 1u) << 4);
}

static __device__ __forceinline__ void mma16816(float* d, uint32_t a0, uint32_t a1,
                                                uint32_t a2, uint32_t a3,
                                                uint32_t b0, uint32_t b1) {
    asm volatile(
        "mma.sync.aligned.m16n8k16.row.col.f32.f16.f16.f32 "
        "{%0,%1,%2,%3}, {%4,%5,%6,%7}, {%8,%9}, {%0,%1,%2,%3};\n"
        : "+f"(d[0]), "+f"(d[1]), "+f"(d[2]), "+f"(d[3])
        : "r"(a0), "r"(a1), "r"(a2), "r"(a3), "r"(b0), "r"(b1));
}

__global__ __launch_bounds__(THREADS, 3)
void parallax_hmma_kernel(const float* __restrict__ img,
                          const int*   __restrict__ idxp,
                          const float* __restrict__ wts,
                          const float* __restrict__ alpha,
                          float*       __restrict__ out)
{
    extern __shared__ char smem[];

    const int tid  = threadIdx.x;
    const int wm   = tid >> 5;          // warp id = m-tile (16 px each)
    const int lane = tid & 31;
    const int g    = lane >> 2;         // groupID
    const int t4   = lane & 3;          // threadID_in_group

    const int c     = blockIdx.z;
    const int x0    = blockIdx.x * 128;
    const int ybase = blockIdx.y * YB;

    // ===== stage image tile: two parity-shifted fp16 copies (division-free) =====
    {
        const float* imgc = img + (size_t)c * IW * IW;
        #pragma unroll 1
        for (int step = 0; step < (IMROWS + 7) / 8; ++step) {
            int r = wm + 8 * step;
            if (r < IMROWS) {
                const float* row = imgc + (size_t)(ybase + r) * IW + x0;
                char* dstrow = smem + r * ROWSTRIDE;
                #pragma unroll
                for (int sub = 0; sub < 5; ++sub) {
                    int slot = lane + 32 * sub;          // 0..159
                    int cp   = slot >= CW;
                    int wd   = slot - CW * cp;
                    int e    = 2 * wd + cp;
                    float f0 = (e     < IMCOLS) ? row[e]     : 0.0f;
                    float f1 = (e + 1 < IMCOLS) ? row[e + 1] : 0.0f;
                    *reinterpret_cast<__half2*>(dstrow + cp * COPY_OFF + wd * 4)
                        = __floats2half2_rn(f0, f1);
                }
            }
        }
    }

    // ===== stage weights: per-lane fragments chunked by k-step, swizzled =====
    // thread owns (ln = tid>>3, w = tid&7):
    //   q = w>>2 (k-step chunk), nh = (w>>1)&1, rr = w&1
    //   k2 = lt4 + 4*rr + 8*q;  l = nh*8 + lg;  j = 2*k2
    {
        const float* wc = wts + (size_t)c * NL * (KS * KS);
        const int ln  = tid >> 3, w = tid & 7;
        const int lt4 = ln & 3,  lg = ln >> 2;
        const int q   = w >> 2,  nh = (w >> 1) & 1, rr = w & 1;
        const int k2  = lt4 + 4 * rr + 8 * q;
        const int l   = nh * 8 + lg;
        const int j   = 2 * k2;
        const bool hasf1 = (j + 1 < KS);
        const float* src = wc + l * (KS * KS) + j;
        char* dst = smem + IMG_BYTES + bswz((uint32_t)(ln * 32 + w * 4));
        #pragma unroll 1
        for (int i = 0; i < KS; ++i) {
            float f0 = src[0];
            float f1 = hasf1 ? src[1] : 0.0f;
            *reinterpret_cast<__half2*>(dst) = __floats2half2_rn(f0, f1);
            src += KS;
            dst += 1024;
        }
    }
    __syncthreads();

    // per-lane A base offset within an image row: element s = wm*16 + g + 2*t4
    const int sb   = wm * 16 + g + 2 * t4;
    const int aoff = ((sb >> 1) << 2) + (sb & 1) * COPY_OFF;
    const char* abase_sm = smem + aoff;
    const uint32_t b0off = bswz((uint32_t)(lane * 32));        // kstep0 chunk
    const uint32_t b1off = bswz((uint32_t)(lane * 32 + 16));   // kstep1 chunk
    const char* wbase_sm = smem + IMG_BYTES;

    // ===== walking pointers for epilogue (init once, step +WOUT per row) =====
    const int id = *idxp;
    const int x  = x0 + wm * 16 + g;
    const int l0 = 2 * t4;
    const float* a_p0 = alpha + (size_t)id * NL * HW + (size_t)l0 * HW
                      + (size_t)ybase * WOUT + x;
    const float* a_p1 = a_p0 + HW;
    const float* a_p8 = a_p0 + 8 * HW;
    const float* a_p9 = a_p0 + 9 * HW;
    float*       op   = out + ((size_t)c * HOUT + ybase) * WOUT + x;

    #pragma unroll 1
    for (int yg = 0; yg < YB / 4; ++yg) {
        const int ygbase = yg * 4;

        float d[4][2][4];
        #pragma unroll
        for (int yy = 0; yy < 4; ++yy)
            #pragma unroll
            for (int nh = 0; nh < 2; ++nh)
                #pragma unroll
                for (int r = 0; r < 4; ++r)
                    d[yy][nh][r] = 0.0f;

        // rolling A window: slot (lr & 3) holds frags of local image row lr
        uint32_t afr[4][5];
        #pragma unroll
        for (int r = 0; r < 4; ++r) {
            const char* arow = abase_sm + (ygbase + r) * ROWSTRIDE;
            #pragma unroll
            for (int q = 0; q < 5; ++q)
                afr[r][q] = *reinterpret_cast<const uint32_t*>(arow + 16 * q);
        }

        // prime B ping-pong buffers with kernel row 0
        uint4 bk0 = *reinterpret_cast<const uint4*>(wbase_sm + b0off);
        uint4 bk1 = *reinterpret_cast<const uint4*>(wbase_sm + b1off);

        #pragma unroll
        for (int i = 0; i < KS; ++i) {
            // kstep0 (k=0..15): frags {A0, A1, A1, A2}, weights bk0
            #pragma unroll
            for (int yy = 0; yy < 4; ++yy) {
                const uint32_t* A = afr[(i + yy) & 3];
                mma16816(d[yy][0], A[0], A[1], A[1], A[2], bk0.x, bk0.y);
                mma16816(d[yy][1], A[0], A[1], A[1], A[2], bk0.z, bk0.w);
            }

            // reload kstep0 chunk for i+1 (bk0 dead) — covered by kstep1 below
            if (i < KS - 1)
                bk0 = *reinterpret_cast<const uint4*>(
                    wbase_sm + (i + 1) * 1024 + b0off);

            // kstep1 (k=16..31): frags {A2, A3, A3, A4}, weights bk1
            #pragma unroll
            for (int yy = 0; yy < 4; ++yy) {
                const uint32_t* A = afr[(i + yy) & 3];
                mma16816(d[yy][0], A[2], A[3], A[3], A[4], bk1.x, bk1.y);
                mma16816(d[yy][1], A[2], A[3], A[3], A[4], bk1.z, bk1.w);
            }

            if (i < KS - 1) {
                // reload kstep1 chunk for i+1 — covered by kstep0 of i+1
                bk1 = *reinterpret_cast<const uint4*>(
                    wbase_sm + (i + 1) * 1024 + b1off);
                // slide A window: row i is now dead; load row i+4 into slot i&3
                const char* arow = abase_sm + (ygbase + i + 4) * ROWSTRIDE;
                #pragma unroll
                for (int q = 0; q < 5; ++q)
                    afr[i & 3][q] = *reinterpret_cast<const uint32_t*>(arow + 16 * q);
            }
        }

        // ===== epilogue: alpha contraction + quad reduce (pointer-walk) =====
        #pragma unroll
        for (int yy = 0; yy < 4; ++yy) {
            float st  = d[yy][0][0] * a_p0[0] + d[yy][0][1] * a_p1[0]
                      + d[yy][1][0] * a_p8[0] + d[yy][1][1] * a_p9[0];
            float st8 = d[yy][0][2] * a_p0[8] + d[yy][0][3] * a_p1[8]
                      + d[yy][1][2] * a_p8[8] + d[yy][1][3] * a_p9[8];

            st  += __shfl_xor_sync(0xFFFFFFFF, st, 1);
            st  += __shfl_xor_sync(0xFFFFFFFF, st, 2);
            st8 += __shfl_xor_sync(0xFFFFFFFF, st8, 1);
            st8 += __shfl_xor_sync(0xFFFFFFFF, st8, 2);

            if (t4 == 0) {
                op[0] = st;
                op[8] = st8;
            }
            a_p0 += WOUT; a_p1 += WOUT; a_p8 += WOUT; a_p9 += WOUT;
            op   += WOUT;
        }
    }
}

extern "C" void kernel_launch(void* const* d_in, const int* in_sizes, int n_in,
                              void* d_out, int out_size)
{
    const float* img   = (const float*)d_in[0];
    const int*   idxp  = (const int*)d_in[1];
    const float* wts   = (const float*)d_in[2];
    const float* alpha = (const float*)d_in[3];
    float*       out   = (float*)d_out;

    cudaFuncSetAttribute(parallax_hmma_kernel,
                         cudaFuncAttributeMaxDynamicSharedMemorySize, SMEM_BYTES);

    dim3 grid(WOUT / 128, HOUT / YB, 3);
    parallax_hmma_kernel<<<grid, THREADS, SMEM_BYTES>>>(img, idxp, wts, alpha, out);
}

// round 14
// speedup vs baseline: 1.1236x; 1.1236x over previous
#include <cuda_runtime.h>
#include <cuda_fp16.h>
#include <stdint.h>

// out[c,y,x] = sum_l alpha[idx,l,y,x] * sum_{i,j} img[c,y+i,x+j] * w[c*16+l,i,j]
//
// HMMA m16n8k16 implicit-im2col (R12 base, YB=8):
//  - rolling 4-slot A register window, slide AFTER kstep1 (row i dead)
//  - B smem chunked BY K-STEP, zero-reg ping-pong reload (>=8 MMAs LDS cover)
//  - bit4-XOR swizzle (conflict-free LDS.128)
//  - pointer-walk epilogue
//  - YB=8: grid 3072 -> wave utilization 98.8% (vs 86.5% at YB=16)
//  - 3 blocks/SM (56 KB smem, ~80 regs)

#define KS     31
#define NL     16
#define HOUT   1024
#define WOUT   1024
#define IW     1054
#define HW     ((size_t)HOUT * WOUT)

#define YB     8               // output rows per block
#define IMROWS (YB + 30)       // 38 staged image rows
#define IMCOLS 158             // 128 + 30 needed columns
#define CW     80              // half2 words per copy per row
#define COPY_OFF   (CW * 4)    // 320 B: parity-shifted copy offset
#define ROWSTRIDE  (2 * CW * 4)          // 640 B per image row (both copies)
#define IMG_BYTES  (IMROWS * ROWSTRIDE)  // 24320
#define W_BYTES    (KS * 32 * 32)        // 31744: [i][lane][8 half2] (swizzled)
#define SMEM_BYTES (IMG_BYTES + W_BYTES) // 56064 -> 3 blocks/SM

#define THREADS 256

static __device__ __forceinline__ uint32_t bswz(uint32_t off) {
    return off ^ (((off >> 7) & 1u) << 4);
}

static __device__ __forceinline__ void mma16816(float* d, uint32_t a0, uint32_t a1,
                                                uint32_t a2, uint32_t a3,
                                                uint32_t b0, uint32_t b1) {
    asm volatile(
        "mma.sync.aligned.m16n8k16.row.col.f32.f16.f16.f32 "
        "{%0,%1,%2,%3}, {%4,%5,%6,%7}, {%8,%9}, {%0,%1,%2,%3};\n"
        : "+f"(d[0]), "+f"(d[1]), "+f"(d[2]), "+f"(d[3])
        : "r"(a0), "r"(a1), "r"(a2), "r"(a3), "r"(b0), "r"(b1));
}

__global__ __launch_bounds__(THREADS, 3)
void parallax_hmma_kernel(const float* __restrict__ img,
                          const int*   __restrict__ idxp,
                          const float* __restrict__ wts,
                          const float* __restrict__ alpha,
                          float*       __restrict__ out)
{
    extern __shared__ char smem[];

    const int tid  = threadIdx.x;
    const int wm   = tid >> 5;          // warp id = m-tile (16 px each)
    const int lane = tid & 31;
    const int g    = lane >> 2;         // groupID
    const int t4   = lane & 3;          // threadID_in_group

    const int c     = blockIdx.z;
    const int x0    = blockIdx.x * 128;
    const int ybase = blockIdx.y * YB;

    // ===== stage image tile: two parity-shifted fp16 copies (division-free) =====
    {
        const float* imgc = img + (size_t)c * IW * IW;
        #pragma unroll 1
        for (int step = 0; step < (IMROWS + 7) / 8; ++step) {
            int r = wm + 8 * step;
            if (r < IMROWS) {
                const float* row = imgc + (size_t)(ybase + r) * IW + x0;
                char* dstrow = smem + r * ROWSTRIDE;
                #pragma unroll
                for (int sub = 0; sub < 5; ++sub) {
                    int slot = lane + 32 * sub;          // 0..159
                    int cp   = slot >= CW;
                    int wd   = slot - CW * cp;
                    int e    = 2 * wd + cp;
                    float f0 = (e     < IMCOLS) ? row[e]     : 0.0f;
                    float f1 = (e + 1 < IMCOLS) ? row[e + 1] : 0.0f;
                    *reinterpret_cast<__half2*>(dstrow + cp * COPY_OFF + wd * 4)
                        = __floats2half2_rn(f0, f1);
                }
            }
        }
    }

    // ===== stage weights: per-lane fragments chunked by k-step, swizzled =====
    // thread owns (ln = tid>>3, w = tid&7):
    //   q = w>>2 (k-step chunk), nh = (w>>1)&1, rr = w&1
    //   k2 = lt4 + 4*rr + 8*q;  l = nh*8 + lg;  j = 2*k2
    {
        const float* wc = wts + (size_t)c * NL * (KS * KS);
        const int ln  = tid >> 3, w = tid & 7;
        const int lt4 = ln & 3,  lg = ln >> 2;
        const int q   = w >> 2,  nh = (w >> 1) & 1, rr = w & 1;
        const int k2  = lt4 + 4 * rr + 8 * q;
        const int l   = nh * 8 + lg;
        const int j   = 2 * k2;
        const bool hasf1 = (j + 1 < KS);
        const float* src = wc + l * (KS * KS) + j;
        char* dst = smem + IMG_BYTES + bswz((uint32_t)(ln * 32 + w * 4));
        #pragma unroll 1
        for (int i = 0; i < KS; ++i) {
            float f0 = src[0];
            float f1 = hasf1 ? src[1] : 0.0f;
            *reinterpret_cast<__half2*>(dst) = __floats2half2_rn(f0, f1);
            src += KS;
            dst += 1024;
        }
    }
    __syncthreads();

    // per-lane A base offset within an image row: element s = wm*16 + g + 2*t4
    const int sb   = wm * 16 + g + 2 * t4;
    const int aoff = ((sb >> 1) << 2) + (sb & 1) * COPY_OFF;
    const char* abase_sm = smem + aoff;
    const uint32_t b0off = bswz((uint32_t)(lane * 32));        // kstep0 chunk
    const uint32_t b1off = bswz((uint32_t)(lane * 32 + 16));   // kstep1 chunk
    const char* wbase_sm = smem + IMG_BYTES;

    // ===== walking pointers for epilogue (init once, step +WOUT per row) =====
    const int id = *idxp;
    const int x  = x0 + wm * 16 + g;
    const int l0 = 2 * t4;
    const float* a_p0 = alpha + (size_t)id * NL * HW + (size_t)l0 * HW
                      + (size_t)ybase * WOUT + x;
    const float* a_p1 = a_p0 + HW;
    const float* a_p8 = a_p0 + 8 * HW;
    const float* a_p9 = a_p0 + 9 * HW;
    float*       op   = out + ((size_t)c * HOUT + ybase) * WOUT + x;

    #pragma unroll 1
    for (int yg = 0; yg < YB / 4; ++yg) {
        const int ygbase = yg * 4;

        float d[4][2][4];
        #pragma unroll
        for (int yy = 0; yy < 4; ++yy)
            #pragma unroll
            for (int nh = 0; nh < 2; ++nh)
                #pragma unroll
                for (int r = 0; r < 4; ++r)
                    d[yy][nh][r] = 0.0f;

        // rolling A window: slot (lr & 3) holds frags of local image row lr
        uint32_t afr[4][5];
        #pragma unroll
        for (int r = 0; r < 4; ++r) {
            const char* arow = abase_sm + (ygbase + r) * ROWSTRIDE;
            #pragma unroll
            for (int q = 0; q < 5; ++q)
                afr[r][q] = *reinterpret_cast<const uint32_t*>(arow + 16 * q);
        }

        // prime B ping-pong buffers with kernel row 0
        uint4 bk0 = *reinterpret_cast<const uint4*>(wbase_sm + b0off);
        uint4 bk1 = *reinterpret_cast<const uint4*>(wbase_sm + b1off);

        #pragma unroll
        for (int i = 0; i < KS; ++i) {
            // kstep0 (k=0..15): frags {A0, A1, A1, A2}, weights bk0
            #pragma unroll
            for (int yy = 0; yy < 4; ++yy) {
                const uint32_t* A = afr[(i + yy) & 3];
                mma16816(d[yy][0], A[0], A[1], A[1], A[2], bk0.x, bk0.y);
                mma16816(d[yy][1], A[0], A[1], A[1], A[2], bk0.z, bk0.w);
            }

            // reload kstep0 chunk for i+1 (bk0 dead) — covered by kstep1 below
            if (i < KS - 1)
                bk0 = *reinterpret_cast<const uint4*>(
                    wbase_sm + (i + 1) * 1024 + b0off);

            // kstep1 (k=16..31): frags {A2, A3, A3, A4}, weights bk1
            #pragma unroll
            for (int yy = 0; yy < 4; ++yy) {
                const uint32_t* A = afr[(i + yy) & 3];
                mma16816(d[yy][0], A[2], A[3], A[3], A[4], bk1.x, bk1.y);
                mma16816(d[yy][1], A[2], A[3], A[3], A[4], bk1.z, bk1.w);
            }

            if (i < KS - 1) {
                // reload kstep1 chunk for i+1 — covered by kstep0 of i+1
                bk1 = *reinterpret_cast<const uint4*>(
                    wbase_sm + (i + 1) * 1024 + b1off);
                // slide A window: row i is now dead; load row i+4 into slot i&3
                const char* arow = abase_sm + (ygbase + i + 4) * ROWSTRIDE;
                #pragma unroll
                for (int q = 0; q < 5; ++q)
                    afr[i & 3][q] = *reinterpret_cast<const uint32_t*>(arow + 16 * q);
            }
        }

        // ===== epilogue: alpha contraction + quad reduce (pointer-walk) =====
        #pragma unroll
        for (int yy = 0; yy < 4; ++yy) {
            float st  = d[yy][0][0] * a_p0[0] + d[yy][0][1] * a_p1[0]
                      + d[yy][1][0] * a_p8[0] + d[yy][1][1] * a_p9[0];
            float st8 = d[yy][0][2] * a_p0[8] + d[yy][0][3] * a_p1[8]
                      + d[yy][1][2] * a_p8[8] + d[yy][1][3] * a_p9[8];

            st  += __shfl_xor_sync(0xFFFFFFFF, st, 1);
            st  += __shfl_xor_sync(0xFFFFFFFF, st, 2);
            st8 += __shfl_xor_sync(0xFFFFFFFF, st8, 1);
            st8 += __shfl_xor_sync(0xFFFFFFFF, st8, 2);

            if (t4 == 0) {
                op[0] = st;
                op[8] = st8;
            }
            a_p0 += WOUT; a_p1 += WOUT; a_p8 += WOUT; a_p9 += WOUT;
            op   += WOUT;
        }
    }
}

extern "C" void kernel_launch(void* const* d_in, const int* in_sizes, int n_in,
                              void* d_out, int out_size)
{
    const float* img   = (const float*)d_in[0];
    const int*   idxp  = (const int*)d_in[1];
    const float* wts   = (const float*)d_in[2];
    const float* alpha = (const float*)d_in[3];
    float*       out   = (float*)d_out;

    cudaFuncSetAttribute(parallax_hmma_kernel,
                         cudaFuncAttributeMaxDynamicSharedMemorySize, SMEM_BYTES);

    dim3 grid(WOUT / 128, HOUT / YB, 3);
    parallax_hmma_kernel<<<grid, THREADS, SMEM_BYTES>>>(img, idxp, wts, alpha, out);
}

// round 15
// speedup vs baseline: 1.2020x; 1.0698x over previous
#include <cuda_runtime.h>
#include <cuda_fp16.h>
#include <stdint.h>

// out[c,y,x] = sum_l alpha[idx,l,y,x] * sum_{i,j} img[c,y+i,x+j] * w[c*16+l,i,j]
//
// HMMA m16n8k16 implicit-im2col (R14 base + weight prepack):
//  - prepack kernel materializes swizzled fragment-ordered fp16 weights ONCE
//    into __device__ global; main kernel weight staging = flat uint4 copy
//  - rolling 4-slot A register window, slide AFTER kstep1
//  - B smem chunked BY K-STEP, zero-reg ping-pong reload
//  - bit4-XOR swizzle (conflict-free LDS.128)
//  - YB=8 (grid 3072, ~99% wave utilization), 3 blocks/SM

#define KS     31
#define NL     16
#define HOUT   1024
#define WOUT   1024
#define IW     1054
#define HW     ((size_t)HOUT * WOUT)

#define YB     8               // output rows per block
#define IMROWS (YB + 30)       // 38 staged image rows
#define IMCOLS 158             // 128 + 30 needed columns
#define CW     80              // half2 words per copy per row
#define COPY_OFF   (CW * 4)    // 320 B: parity-shifted copy offset
#define ROWSTRIDE  (2 * CW * 4)          // 640 B per image row (both copies)
#define IMG_BYTES  (IMROWS * ROWSTRIDE)  // 24320
#define W_BYTES    (KS * 32 * 32)        // 31744: [i][lane][8 half2] (swizzled)
#define SMEM_BYTES (IMG_BYTES + W_BYTES) // 56064 -> 3 blocks/SM

#define THREADS 256

static __device__ __forceinline__ uint32_t bswz(uint32_t off) {
    return off ^ (((off >> 7) & 1u) << 4);
}

static __device__ __forceinline__ void mma16816(float* d, uint32_t a0, uint32_t a1,
                                                uint32_t a2, uint32_t a3,
                                                uint32_t b0, uint32_t b1) {
    asm volatile(
        "mma.sync.aligned.m16n8k16.row.col.f32.f16.f16.f32 "
        "{%0,%1,%2,%3}, {%4,%5,%6,%7}, {%8,%9}, {%0,%1,%2,%3};\n"
        : "+f"(d[0]), "+f"(d[1]), "+f"(d[2]), "+f"(d[3])
        : "r"(a0), "r"(a1), "r"(a2), "r"(a3), "r"(b0), "r"(b1));
}

// block-invariant packed weights: [c][i][lane][8 half2], bswz-swizzled
__device__ __align__(16) unsigned char g_wpack[3 * KS * 1024];

// ===== prepack: fp32 weights -> fragment-ordered swizzled fp16 =====
__global__ void prepack_weights(const float* __restrict__ wts) {
    int idx = blockIdx.x * blockDim.x + threadIdx.x;   // one half2 each
    const int total = 3 * KS * 256;
    if (idx >= total) return;
    int c   = idx / (KS * 256);
    int rem = idx - c * (KS * 256);
    int i   = rem >> 8;
    int r2  = rem & 255;
    int ln  = r2 >> 3, w = r2 & 7;
    int lt4 = ln & 3,  lg = ln >> 2;
    int q   = w >> 2,  nh = (w >> 1) & 1, rr = w & 1;
    int k2  = lt4 + 4 * rr + 8 * q;
    int l   = nh * 8 + lg;
    int j   = 2 * k2;
    const float* wc = wts + (size_t)c * NL * (KS * KS);
    float f0 = wc[l * (KS * KS) + i * KS + j];
    float f1 = (j + 1 < KS) ? wc[l * (KS * KS) + i * KS + j + 1] : 0.0f;
    *reinterpret_cast<__half2*>(
        g_wpack + (size_t)c * (KS * 1024) + i * 1024
        + bswz((uint32_t)(ln * 32 + w * 4))) = __floats2half2_rn(f0, f1);
}

__global__ __launch_bounds__(THREADS, 3)
void parallax_hmma_kernel(const float* __restrict__ img,
                          const int*   __restrict__ idxp,
                          const float* __restrict__ alpha,
                          float*       __restrict__ out)
{
    extern __shared__ char smem[];

    const int tid  = threadIdx.x;
    const int wm   = tid >> 5;          // warp id = m-tile (16 px each)
    const int lane = tid & 31;
    const int g    = lane >> 2;         // groupID
    const int t4   = lane & 3;          // threadID_in_group

    const int c     = blockIdx.z;
    const int x0    = blockIdx.x * 128;
    const int ybase = blockIdx.y * YB;

    // ===== stage image tile: two parity-shifted fp16 copies (division-free) =====
    {
        const float* imgc = img + (size_t)c * IW * IW;
        #pragma unroll 1
        for (int step = 0; step < (IMROWS + 7) / 8; ++step) {
            int r = wm + 8 * step;
            if (r < IMROWS) {
                const float* row = imgc + (size_t)(ybase + r) * IW + x0;
                char* dstrow = smem + r * ROWSTRIDE;
                #pragma unroll
                for (int sub = 0; sub < 5; ++sub) {
                    int slot = lane + 32 * sub;          // 0..159
                    int cp   = slot >= CW;
                    int wd   = slot - CW * cp;
                    int e    = 2 * wd + cp;
                    float f0 = (e     < IMCOLS) ? row[e]     : 0.0f;
                    float f1 = (e + 1 < IMCOLS) ? row[e + 1] : 0.0f;
                    *reinterpret_cast<__half2*>(dstrow + cp * COPY_OFF + wd * 4)
                        = __floats2half2_rn(f0, f1);
                }
            }
        }
    }

    // ===== stage weights: flat 16B copy of prepacked block-invariant data =====
    {
        const uint4* srcw = reinterpret_cast<const uint4*>(
            g_wpack + (size_t)c * (KS * 1024));
        uint4* dstw = reinterpret_cast<uint4*>(smem + IMG_BYTES);
        #pragma unroll
        for (int t = tid; t < KS * 64; t += THREADS)   // 1984 uint4
            dstw[t] = srcw[t];
    }
    __syncthreads();

    // per-lane A base offset within an image row: element s = wm*16 + g + 2*t4
    const int sb   = wm * 16 + g + 2 * t4;
    const int aoff = ((sb >> 1) << 2) + (sb & 1) * COPY_OFF;
    const char* abase_sm = smem + aoff;
    const uint32_t b0off = bswz((uint32_t)(lane * 32));        // kstep0 chunk
    const uint32_t b1off = bswz((uint32_t)(lane * 32 + 16));   // kstep1 chunk
    const char* wbase_sm = smem + IMG_BYTES;

    // ===== walking pointers for epilogue (init once, step +WOUT per row) =====
    const int id = *idxp;
    const int x  = x0 + wm * 16 + g;
    const int l0 = 2 * t4;
    const float* a_p0 = alpha + (size_t)id * NL * HW + (size_t)l0 * HW
                      + (size_t)ybase * WOUT + x;
    const float* a_p1 = a_p0 + HW;
    const float* a_p8 = a_p0 + 8 * HW;
    const float* a_p9 = a_p0 + 9 * HW;
    float*       op   = out + ((size_t)c * HOUT + ybase) * WOUT + x;

    #pragma unroll 1
    for (int yg = 0; yg < YB / 4; ++yg) {
        const int ygbase = yg * 4;

        float d[4][2][4];
        #pragma unroll
        for (int yy = 0; yy < 4; ++yy)
            #pragma unroll
            for (int nh = 0; nh < 2; ++nh)
                #pragma unroll
                for (int r = 0; r < 4; ++r)
                    d[yy][nh][r] = 0.0f;

        // rolling A window: slot (lr & 3) holds frags of local image row lr
        uint32_t afr[4][5];
        #pragma unroll
        for (int r = 0; r < 4; ++r) {
            const char* arow = abase_sm + (ygbase + r) * ROWSTRIDE;
            #pragma unroll
            for (int q = 0; q < 5; ++q)
                afr[r][q] = *reinterpret_cast<const uint32_t*>(arow + 16 * q);
        }

        // prime B ping-pong buffers with kernel row 0
        uint4 bk0 = *reinterpret_cast<const uint4*>(wbase_sm + b0off);
        uint4 bk1 = *reinterpret_cast<const uint4*>(wbase_sm + b1off);

        #pragma unroll
        for (int i = 0; i < KS; ++i) {
            // kstep0 (k=0..15): frags {A0, A1, A1, A2}, weights bk0
            #pragma unroll
            for (int yy = 0; yy < 4; ++yy) {
                const uint32_t* A = afr[(i + yy) & 3];
                mma16816(d[yy][0], A[0], A[1], A[1], A[2], bk0.x, bk0.y);
                mma16816(d[yy][1], A[0], A[1], A[1], A[2], bk0.z, bk0.w);
            }

            // reload kstep0 chunk for i+1 (bk0 dead) — covered by kstep1 below
            if (i < KS - 1)
                bk0 = *reinterpret_cast<const uint4*>(
                    wbase_sm + (i + 1) * 1024 + b0off);

            // kstep1 (k=16..31): frags {A2, A3, A3, A4}, weights bk1
            #pragma unroll
            for (int yy = 0; yy < 4; ++yy) {
                const uint32_t* A = afr[(i + yy) & 3];
                mma16816(d[yy][0], A[2], A[3], A[3], A[4], bk1.x, bk1.y);
                mma16816(d[yy][1], A[2], A[3], A[3], A[4], bk1.z, bk1.w);
            }

            if (i < KS - 1) {
                // reload kstep1 chunk for i+1 — covered by kstep0 of i+1
                bk1 = *reinterpret_cast<const uint4*>(
                    wbase_sm + (i + 1) * 1024 + b1off);
                // slide A window: row i is now dead; load row i+4 into slot i&3
                const char* arow = abase_sm + (ygbase + i + 4) * ROWSTRIDE;
                #pragma unroll
                for (int q = 0; q < 5; ++q)
                    afr[i & 3][q] = *reinterpret_cast<const uint32_t*>(arow + 16 * q);
            }
        }

        // ===== epilogue: alpha contraction + quad reduce (pointer-walk) =====
        #pragma unroll
        for (int yy = 0; yy < 4; ++yy) {
            float st  = d[yy][0][0] * a_p0[0] + d[yy][0][1] * a_p1[0]
                      + d[yy][1][0] * a_p8[0] + d[yy][1][1] * a_p9[0];
            float st8 = d[yy][0][2] * a_p0[8] + d[yy][0][3] * a_p1[8]
                      + d[yy][1][2] * a_p8[8] + d[yy][1][3] * a_p9[8];

            st  += __shfl_xor_sync(0xFFFFFFFF, st, 1);
            st  += __shfl_xor_sync(0xFFFFFFFF, st, 2);
            st8 += __shfl_xor_sync(0xFFFFFFFF, st8, 1);
            st8 += __shfl_xor_sync(0xFFFFFFFF, st8, 2);

            if (t4 == 0) {
                op[0] = st;
                op[8] = st8;
            }
            a_p0 += WOUT; a_p1 += WOUT; a_p8 += WOUT; a_p9 += WOUT;
            op   += WOUT;
        }
    }
}

extern "C" void kernel_launch(void* const* d_in, const int* in_sizes, int n_in,
                              void* d_out, int out_size)
{
    const float* img   = (const float*)d_in[0];
    const int*   idxp  = (const int*)d_in[1];
    const float* wts   = (const float*)d_in[2];
    const float* alpha = (const float*)d_in[3];
    float*       out   = (float*)d_out;

    // one-shot (per launch) weight prepack: block-invariant fragment layout
    const int total = 3 * KS * 256;
    prepack_weights<<<(total + 255) / 256, 256>>>(wts);

    cudaFuncSetAttribute(parallax_hmma_kernel,
                         cudaFuncAttributeMaxDynamicSharedMemorySize, SMEM_BYTES);

    dim3 grid(WOUT / 128, HOUT / YB, 3);
    parallax_hmma_kernel<<<grid, THREADS, SMEM_BYTES>>>(img, idxp, alpha, out);
}